// round 13
// baseline (speedup 1.0000x reference)
#include <cuda_runtime.h>

// Problem constants (fixed by the dataset)
#define Nn 8
#define Kk 16
#define Hh 256
#define Ww 256
#define Cc 4
#define Pp 100000
#define HW (Hh * Ww)          // 65536
#define NPIX (Nn * HW)        // 524288
#define WEPS 2e-5f            // tail-slot gather skip threshold

// Scratch: ptclds transposed to AoS (P x float4) — __device__ global, no alloc.
__device__ float4 g_ptcld_aos[Pp];

// Kernel 1: transpose (C,P) -> AoS float4[P]
__global__ void transpose_ptcld_kernel(const float* __restrict__ ptclds) {
    int i = blockIdx.x * blockDim.x + threadIdx.x;
    if (i < Pp) {
        float4 v;
        v.x = ptclds[0 * Pp + i];
        v.y = ptclds[1 * Pp + i];
        v.z = ptclds[2 * Pp + i];
        v.w = ptclds[3 * Pp + i];
        g_ptcld_aos[i] = v;
    }
}

// Kernel 2: FULLY BRANCHLESS. 1 thread/pixel.
// R12 finding: the ~12-16 divergent `if {gather; fma}` arms compile to
// BSSY/BSYNC blocks (~33-56cyc each) — hundreds of serial cycles/thread.
// Fix: unconditional gathers from MASKED indices (invalid/pruned lanes ->
// index 0, one shared L1-hot line, ~+1 wavefront per gather), unconditional
// FMAs with weights that are exactly 0 for invalid slots. Zero branches,
// zero divergence replays; wavefront budget unchanged vs predicated code.
__global__ __launch_bounds__(256, 3) void composite_kernel(
    const int*   __restrict__ fragments,   // (N,K,H,W)
    const float* __restrict__ alphas,      // (N,K,H,W)
    const float* __restrict__ background,  // (3,)
    float*       __restrict__ out)         // (N,C,H,W)
{
    const int pix = blockIdx.x * blockDim.x + threadIdx.x;
    const int n  = pix >> 16;          // pix / HW
    const int hw = pix & (HW - 1);     // pix % HW

    const int base = n * (Kk * HW) + hw;
    float* outp = out + n * (Cc * HW) + hw;

    // 16 fragment loads (independent, coalesced).
    int f[Kk];
    #pragma unroll
    for (int k = 0; k < Kk; ++k) f[k] = fragments[base + k * HW];

    // First-half gathers: unconditional, index clamped to 0 (IMNMX+LDG,
    // no branch). Issued immediately behind the fragment loads.
    float4 p[8];
    #pragma unroll
    for (int j = 0; j < 8; ++j) {
        const int idx = (f[j] >= 0) ? f[j] : 0;
        p[j] = g_ptcld_aos[idx];
    }

    // 16 alpha loads — overlap the in-flight gathers.
    float w[Kk];
    #pragma unroll
    for (int k = 0; k < Kk; ++k) w[k] = alphas[base + k * HW];

    // Weight chain: w[k] = a_k * prod_{j<k}(1-a_j); invalid slots -> a=0
    // (so their weight is EXACTLY 0 and the unconditional FMA is a no-op).
    {
        float T = 1.0f;
        #pragma unroll
        for (int k = 0; k < Kk; ++k) {
            const float a = (f[k] >= 0) ? w[k] : 0.0f;
            w[k] = a * T;
            T = T - a * T;              // T *= (1 - a), single FFMA
        }
    }

    float r = 0.f, g = 0.f, b = 0.f, acc = 0.f;

    // ---- half 1: unconditional FMAs (w==0 for invalid slots) ----
    #pragma unroll
    for (int j = 0; j < 8; ++j) {
        r   = fmaf(w[j], p[j].x, r);
        g   = fmaf(w[j], p[j].y, g);
        b   = fmaf(w[j], p[j].z, b);
        acc = fmaf(w[j], p[j].w, acc);
    }

    // ---- half 2: masked-index gathers + masked-weight FMAs, no branch ----
    #pragma unroll
    for (int j = 0; j < 8; ++j) {
        const int k = 8 + j;
        const bool m = (f[k] >= 0) && (w[k] > WEPS);
        const int idx = m ? f[k] : 0;        // pruned lanes share line 0
        const float wm = m ? w[k] : 0.0f;
        const float4 q = g_ptcld_aos[idx];
        r   = fmaf(wm, q.x, r);
        g   = fmaf(wm, q.y, g);
        b   = fmaf(wm, q.z, b);
        acc = fmaf(wm, q.w, acc);
    }

    // Background fill via selects (no branch).
    const bool bg = (f[0] < 0);
    r   = bg ? background[0] : r;
    g   = bg ? background[1] : g;
    b   = bg ? background[2] : b;
    acc = bg ? 1.0f          : acc;

    outp[0 * HW] = r;
    outp[1 * HW] = g;
    outp[2 * HW] = b;
    outp[3 * HW] = acc;
}

extern "C" void kernel_launch(void* const* d_in, const int* in_sizes, int n_in,
                              void* d_out, int out_size) {
    const int*   fragments  = (const int*)  d_in[0];  // (N,K,H,W) int32
    const float* alphas     = (const float*)d_in[1];  // (N,K,H,W) f32
    const float* ptclds     = (const float*)d_in[2];  // (C,P) f32
    const float* background = (const float*)d_in[3];  // (3,) f32
    float* out = (float*)d_out;                       // (N,C,H,W) f32

    transpose_ptcld_kernel<<<(Pp + 255) / 256, 256>>>(ptclds);
    composite_kernel<<<NPIX / 256, 256>>>(fragments, alphas, background, out);
}